// round 13
// baseline (speedup 1.0000x reference)
#include <cuda_runtime.h>
#include <cuda_fp16.h>
#include <stdint.h>
#include <string.h>

// Problem constants
#define IN_F   2048
#define OUTF   512
#define NB     8
#define BATCH  16

// Packed bits: g_pkw[fb32][out*8+lane] : uint32. Bit j holds the binarized
// weight for f = fb32*32 + j, column out*8+lane. Independent of batch.
// Dims: 64 x 4096 = 262144 words = 1 MB.
__device__ uint32_t g_pkw[64 * 4096];

static __device__ __forceinline__ __half2 u2h2(uint32_t u) {
    __half2 h; memcpy(&h, &u, 4); return h;
}
static __device__ __forceinline__ uint32_t h22u(__half2 h) {
    uint32_t u; memcpy(&u, &h, 4); return u;
}

// ---------------------------------------------------------------------------
// Pack kernel: binarize weight (>= 0.5), 1 bit per f, 32 f per word.
// ---------------------------------------------------------------------------
__global__ void pack_kernel(const float* __restrict__ w) {
    int idx = blockIdx.x * blockDim.x + threadIdx.x;
    int fb32 = idx >> 12;
    int col  = idx & 4095;
    uint32_t word = 0;
#pragma unroll
    for (int j = 0; j < 32; j++) {
        float v = __ldg(w + (size_t)(fb32 * 32 + j) * 4096 + col);
        word |= (v >= 0.5f ? 1u : 0u) << j;
    }
    g_pkw[idx] = word;
}

// ---------------------------------------------------------------------------
// Scan kernel: LANE-WAVEFRONT, no shfl. Thread = lane k (sub=0..7) of
// row-pair {b0,b0+8}; state = one half2. Lane k executes f-step t at
// iteration i = t + k. Carry: c for f-step t = mj of lane k-1 at f-step t-1,
// produced at iteration i-2 -> exchanged via a smem mailbox (STS this iter,
// LDS consumed two iters later; same-warp in-order, no sync). Lane 0 of each
// row reads an always-zero slot (no masking op).
// CSA step (bit-identical per-lane sequence to R12, canary 0.0006271157):
//   a=xu&m; ga=fma(a,-2,1); r=fma(s,ga,a); m1=s*a; mj=fma(c,r,m1);
//   gc=fma(c,-2,1); s'=fma(r,gc,c)
// Weight bit for (iter i, lane k): bit (i&31) of funnelshift_l(w_prev,w_cur,k)
// (one funnel per 32-chunk). x prefetched one iteration ahead.
// Grid: 128 blocks x 256 threads = 1024 warps = 2 warps/SMSP on 128 SMs.
// ---------------------------------------------------------------------------
__global__ void __launch_bounds__(256, 1)
scan_kernel(const float* __restrict__ x, float* __restrict__ out) {
    __shared__ uint32_t sx8[2080];      // [8+f] = {half x[b0,f], half x[b0+8,f]}; pads 0
    __shared__ uint32_t carr[8 * 40];   // per warp: [0..31] mj slots, [39] zero

    const int tid = threadIdx.x;
    const int blk = blockIdx.x;
    const int b0 = blk >> 4;                 // 0..7 ; pair row is b0+8
    const int out_base = (blk & 15) << 5;    // 32 outs per block

    const float* xa = x + b0 * IN_F;
    const float* xb = x + (b0 + 8) * IN_F;
#pragma unroll
    for (int i = 0; i < IN_F / 256; i++) {
        int k = tid + i * 256;
        sx8[8 + k] = h22u(__halves2half2(__float2half(xa[k]), __float2half(xb[k])));
    }
    // zero pads and carry mailboxes
    if (tid < 8)  sx8[tid] = 0;
    if (tid < 24) sx8[2056 + tid] = 0;
    for (int t = tid; t < 8 * 40; t += 256) carr[t] = 0;
    __syncthreads();

    const int sub  = tid & 7;                // lane k within row-pair
    const int lane = tid & 31;
    const int wid  = tid >> 5;
    volatile uint32_t* cw = carr + wid * 40 + lane;                    // write
    volatile uint32_t* cr = carr + wid * 40 + (sub ? lane - 1 : 39);   // read
    const uint32_t* pk = g_pkw + out_base * 8 + tid;   // + fb32*4096 per chunk
    const __half2 neg2 = __float2half2_rn(-2.0f);
    const __half2 one  = __float2half2_rn(1.0f);

    __half2 s = __float2half2_rn(0.0f);
    uint32_t c_use = 0, c_p1 = 0;            // carries for iters i, i+1
    uint32_t xv = sx8[8 - sub];              // x for iter 0 (pad 0 if f<0)

    uint32_t w_cur = __ldg(pk);
    uint32_t w_prev = 0;

    // One wavefront iteration. Returns nothing; updates s and the pipelines.
    // mk = mask for this lane's current f (0 if f<0 or bit==0).
    auto iterstep = [&](uint32_t mk, int xidx_next) {
        __half2 a  = u2h2(xv & mk);
        __half2 cc = u2h2(c_use);
        __half2 ga = __hfma2(a, neg2, one);
        __half2 r  = __hfma2(s, ga, a);      // xor(s, a)
        __half2 m1 = __hmul2(s, a);
        __half2 mj = __hfma2(cc, r, m1);     // maj(s, a, c)
        __half2 gc = __hfma2(cc, neg2, one);
        s = __hfma2(r, gc, cc);              // xor(r, c)
        *cw = h22u(mj);                      // STS: consumed 2 iters later
        uint32_t cl = *cr;                   // LDS: carry for iter i+2
        uint32_t xn = sx8[xidx_next];        // x for iter i+1
        c_use = c_p1; c_p1 = cl;
        xv = xn;
    };

#pragma unroll 1
    for (int m = 0; m < 64; m++) {
        uint32_t w_next = 0;
        if (m < 63) w_next = __ldg(pk + (m + 1) * 4096);
        // bit u of wsh == weight bit for f = 32m + u - sub (0 for f<0)
        uint32_t wsh = __funnelshift_l(w_prev, w_cur, sub);
        const int ib = m * 32;
#pragma unroll
        for (int u = 0; u < 32; u++) {
            uint32_t mk = (uint32_t)(((int32_t)(wsh << (31 - u))) >> 31);
            iterstep(mk, 8 + ib + u + 1 - sub);
        }
        w_prev = w_cur; w_cur = w_next;
    }

    // Epilogue: 8 iterations drain the wavefront (lane k finishes f=2047 at
    // iter 2047+k) and capture the final carry (read at iter 2048+k).
    uint32_t c_fin = 0;
    uint32_t wshE = __funnelshift_l(w_prev, 0u, sub);  // w_prev = word 63
#pragma unroll
    for (int e = 0; e < 8; e++) {
        if (sub == e) c_fin = c_use;         // final carry for lane e
        uint32_t mk = (uint32_t)(((int32_t)(wshE << (31 - e))) >> 31);
        __half2 a  = u2h2(xv & mk);
        __half2 cc = u2h2(c_use);
        __half2 ga = __hfma2(a, neg2, one);
        __half2 r  = __hfma2(s, ga, a);
        __half2 m1 = __hmul2(s, a);
        __half2 mj = __hfma2(cc, r, m1);
        __half2 gc = __hfma2(cc, neg2, one);
        __half2 sn = __hfma2(r, gc, cc);
        if (sub > e) s = sn;                 // freeze finished lanes
        *cw = h22u(mj);
        uint32_t cl = *cr;
        uint32_t xn = sx8[8 + 2048 + e + 1 - sub];
        c_use = c_p1; c_p1 = cl;
        xv = xn;
    }

    // Output float32 (layout identical to R12): s at out[b*4096 + o*8 + k],
    // c at +65536 floats; rows b0 / b0+8 from the half2 halves.
    const int obase = b0 * 4096 + out_base * 8 + tid;
    float2 sf = __half22float2(s);
    float2 cf = __half22float2(u2h2(c_fin));
    out[obase]                 = sf.x;
    out[obase + 32768]         = sf.y;
    out[65536 + obase]         = cf.x;
    out[65536 + obase + 32768] = cf.y;
}

// ---------------------------------------------------------------------------
extern "C" void kernel_launch(void* const* d_in, const int* in_sizes, int n_in,
                              void* d_out, int out_size) {
    const float* x  = (const float*)d_in[0];   // (16, 2048) fp32
    const float* wt = (const float*)d_in[1];   // (2048, 4096) fp32
    float* out = (float*)d_out;                // 131072 fp32: [s | c]

    pack_kernel<<<1024, 256>>>(wt);
    scan_kernel<<<128, 256>>>(x, out);
}

// round 14
// speedup vs baseline: 1.3982x; 1.3982x over previous
#include <cuda_runtime.h>
#include <cuda_fp16.h>
#include <stdint.h>
#include <string.h>

// Problem constants
#define IN_F   2048
#define OUTF   512
#define NB     8
#define BATCH  16

// Packed bits: g_pkw[fb16][out*4+sub] : uint32. Bit pair (2j, 2j+1) holds the
// binarized weights for f = fb16*16 + j, columns out*8 + 2*sub + {0,1}.
// Independent of batch. Dims: 128 x 2048 = 262144 words = 1 MB.
__device__ uint32_t g_pkw[128 * 2048];

static __device__ __forceinline__ __half2 u2h2(uint32_t u) {
    __half2 h; memcpy(&h, &u, 4); return h;
}
static __device__ __forceinline__ uint32_t h22u(__half2 h) {
    uint32_t u; memcpy(&u, &h, 4); return u;
}

// ---------------------------------------------------------------------------
// Pack kernel: binarize weight (>= 0.5), 2 bits per f (adjacent columns),
// 16 f per word. idx = fb16*2048 + (out*4 + sub); columns rem*2, rem*2+1.
// ---------------------------------------------------------------------------
__global__ void pack_kernel(const float* __restrict__ w) {
    int idx = blockIdx.x * blockDim.x + threadIdx.x;
    int fb16 = idx >> 11;         // f-chunk of 16
    int rem  = idx & 2047;        // out*4 + sub -> column base = rem*2
    const float2* wp = reinterpret_cast<const float2*>(w) + rem;
    uint32_t word = 0;
#pragma unroll
    for (int j = 0; j < 16; j++) {
        float2 v = __ldg(wp + (size_t)(fb16 * 16 + j) * 2048);
        word |= ((v.x >= 0.5f ? 1u : 0u) | (v.y >= 0.5f ? 2u : 0u)) << (2 * j);
    }
    g_pkw[idx] = word;
}

// ---------------------------------------------------------------------------
// Scan kernel -- EXACT R8 structure (best wall-clock), with x-quad prefetch
// one chunk ahead and the zmask-AND hoisted to rotation time.
// Thread sub in {0..3} owns lanes {2sub, 2sub+1} of row-pair (b0, b0+8):
// half2 state A = lane 2sub, B = lane 2sub+1 (each packs the two batch rows).
// CSA step per half2 (6 fp16 fma ops, R8 form -- g factors depend on the
// state already in registers, keeping the a-path off the chain):
//   g1 = fma(s,-2,1); r = fma(a,g1,s); m1 = s*a; mj = fma(c,r,m1);
//   g2 = fma(r,-2,1); s' = fma(c,g2,r)
// SKEWED PIPELINE: iteration i runs A-step(f=i-1) then B-step(f=i);
// cB(i)=mjA(i) same-iteration register; cA(i-1)=neighbor mjB(i-2) via a shfl
// issued 2 iterations earlier. Both chains start from (s=0,c=0).
// Grid: 128 blocks x 128 threads = 512 warps = 1 warp/SMSP on 128 SMs.
// ---------------------------------------------------------------------------
__global__ void __launch_bounds__(128, 1)
scan_kernel(const float* __restrict__ x, float* __restrict__ out) {
    __shared__ uint32_t sx[IN_F];   // {half(x[b0,f]), half(x[b0+8,f])}

    const int tid = threadIdx.x;
    const int blk = blockIdx.x;
    const int b0 = blk >> 4;                 // 0..7 ; pair row is b0+8
    const int out_base = (blk & 15) << 5;    // 32 outs per block

    const float* xa = x + b0 * IN_F;
    const float* xb = x + (b0 + 8) * IN_F;
#pragma unroll
    for (int i = 0; i < IN_F / 128; i++) {
        int k = tid + i * 128;
        sx[k] = h22u(__halves2half2(__float2half(xa[k]), __float2half(xb[k])));
    }
    __syncthreads();

    const int sub  = tid & 3;
    const int lane = tid & 31;
    const int srcl = sub ? (lane - 1) : lane;       // carry source lane
    const uint32_t zmask = sub ? 0xFFFFFFFFu : 0u;  // lane-0 carry-in is 0
    const uint32_t* pk = g_pkw + out_base * 4 + tid;   // + fb16*2048 per chunk
    const __half2 neg2 = __float2half2_rn(-2.0f);
    const __half2 one  = __float2half2_rn(1.0f);
    const __half2 zero = __float2half2_rn(0.0f);

    // sign-extend bit `b` of v to a full mask
    auto sext = [](uint32_t v, int b) {
        return (uint32_t)(((int32_t)(v << (31 - b))) >> 31);
    };

    __half2 sA = zero, sB = zero;
    uint32_t p1 = 0;                    // shfl issued last iteration
    uint32_t p2z = 0;                   // zmask-applied shfl from 2 iters ago

    // One pipelined iteration: A-step(f-1) then B-step(f).
    auto stepAB = [&](uint32_t mAu, uint32_t xuA, uint32_t mBu, uint32_t xuB) {
        // ---- A-step (f = i-1); cA = 2-iteration-old neighbor mjB ----
        __half2 aA  = u2h2(xuA & mAu);
        __half2 cAv = u2h2(p2z);
        __half2 m1A = __hmul2(sA, aA);
        __half2 g1A = __hfma2(sA, neg2, one);
        __half2 rA  = __hfma2(aA, g1A, sA);
        __half2 mjA = __hfma2(cAv, rA, m1A);
        __half2 g2A = __hfma2(rA, neg2, one);
        sA = __hfma2(cAv, g2A, rA);
        // ---- B-step (f = i); cB = mjA from THIS iteration ----
        __half2 aB  = u2h2(xuB & mBu);
        __half2 m1B = __hmul2(sB, aB);
        __half2 g1B = __hfma2(sB, neg2, one);
        __half2 rB  = __hfma2(aB, g1B, sB);
        __half2 mjB = __hfma2(mjA, rB, m1B);
        __half2 g2B = __hfma2(rB, neg2, one);
        sB = __hfma2(mjA, g2B, rB);
        // ---- carry exchange; zmask applied at rotation (off-chain) ----
        p2z = p1 & zmask;
        p1 = __shfl_sync(0xFFFFFFFFu, h22u(mjB), srcl);
    };

    const uint4* sx4 = reinterpret_cast<const uint4*>(sx);

    uint32_t w = __ldg(pk);
    uint32_t wprev = 0;                 // bits for f<0 read as 0 (identity)
    uint32_t xu_lag = 0;

    // Prefetch chunk 0's x quads.
    uint4 q0 = sx4[0], q1 = sx4[1], q2 = sx4[2], q3 = sx4[3];

#pragma unroll 1
    for (int fb16 = 0; fb16 < 128; fb16++) {
        uint32_t wnext = 0;
        uint4 n0, n1, n2, n3;
        if (fb16 < 127) {
            wnext = __ldg(pk + (fb16 + 1) * 2048);
            const uint4* pn = sx4 + (fb16 + 1) * 4;
            n0 = pn[0]; n1 = pn[1]; n2 = pn[2]; n3 = pn[3];
        } else {
            n0 = n1 = n2 = n3 = make_uint4(0, 0, 0, 0);
        }
        stepAB(sext(wprev, 30), xu_lag, sext(w, 1),  q0.x);
        stepAB(sext(w, 0),  q0.x, sext(w, 3),  q0.y);
        stepAB(sext(w, 2),  q0.y, sext(w, 5),  q0.z);
        stepAB(sext(w, 4),  q0.z, sext(w, 7),  q0.w);
        stepAB(sext(w, 6),  q0.w, sext(w, 9),  q1.x);
        stepAB(sext(w, 8),  q1.x, sext(w, 11), q1.y);
        stepAB(sext(w, 10), q1.y, sext(w, 13), q1.z);
        stepAB(sext(w, 12), q1.z, sext(w, 15), q1.w);
        stepAB(sext(w, 14), q1.w, sext(w, 17), q2.x);
        stepAB(sext(w, 16), q2.x, sext(w, 19), q2.y);
        stepAB(sext(w, 18), q2.y, sext(w, 21), q2.z);
        stepAB(sext(w, 20), q2.z, sext(w, 23), q2.w);
        stepAB(sext(w, 22), q2.w, sext(w, 25), q3.x);
        stepAB(sext(w, 24), q3.x, sext(w, 27), q3.y);
        stepAB(sext(w, 26), q3.y, sext(w, 29), q3.z);
        stepAB(sext(w, 28), q3.z, sext(w, 31), q3.w);
        xu_lag = q3.w;
        wprev = w;
        w = wnext;
        q0 = n0; q1 = n1; q2 = n2; q3 = n3;
    }

    // Drain: final A-step (f = 2047). cA = p2z = zmasked shfl(mjB(2046)).
    __half2 cB_fin, cA_fin;
    {
        uint32_t mAu = sext(wprev, 30);
        __half2 aA  = u2h2(xu_lag & mAu);
        __half2 cAv = u2h2(p2z);
        __half2 m1A = __hmul2(sA, aA);
        __half2 g1A = __hfma2(sA, neg2, one);
        __half2 rA  = __hfma2(aA, g1A, sA);
        __half2 mjA = __hfma2(cAv, rA, m1A);
        __half2 g2A = __hfma2(rA, neg2, one);
        sA = __hfma2(cAv, g2A, rA);
        cB_fin = mjA;                        // carry into lane 2sub+1
        cA_fin = u2h2(p1 & zmask);           // shfl(mjB(2047)) from last iter
    }

    // Output float32. Thread sub holds lanes (2sub, 2sub+1) of rows b0, b0+8.
    // s at out[b*4096 + o*8 + lane], c at +65536 floats.
    const int out_i = out_base + (tid >> 2);
    const int baseA = b0 * 4096 + out_i * 8 + 2 * sub;        // row b0
    const int baseB = baseA + 8 * 4096;                       // row b0+8
    float2 sAf = __half22float2(sA), cAf = __half22float2(cA_fin);
    float2 sBf = __half22float2(sB), cBf = __half22float2(cB_fin);
    out[baseA]             = sAf.x;   // row b0,   lane 2sub
    out[baseA + 1]         = sBf.x;   // row b0,   lane 2sub+1
    out[baseB]             = sAf.y;   // row b0+8, lane 2sub
    out[baseB + 1]         = sBf.y;
    out[65536 + baseA]     = cAf.x;
    out[65536 + baseA + 1] = cBf.x;
    out[65536 + baseB]     = cAf.y;
    out[65536 + baseB + 1] = cBf.y;
}

// ---------------------------------------------------------------------------
extern "C" void kernel_launch(void* const* d_in, const int* in_sizes, int n_in,
                              void* d_out, int out_size) {
    const float* x  = (const float*)d_in[0];   // (16, 2048) fp32
    const float* wt = (const float*)d_in[1];   // (2048, 4096) fp32
    float* out = (float*)d_out;                // 131072 fp32: [s | c]

    pack_kernel<<<1024, 256>>>(wt);
    scan_kernel<<<128, 128>>>(x, out);
}

// round 15
// speedup vs baseline: 1.4480x; 1.0356x over previous
#include <cuda_runtime.h>
#include <cuda_fp16.h>
#include <stdint.h>
#include <string.h>

// Problem constants
#define IN_F   2048
#define OUTF   512
#define NB     8
#define BATCH  16

// Packed bits: g_pkw[fb16][out*4+sub] : uint32. Bit pair (2j, 2j+1) holds the
// binarized weights for f = fb16*16 + j, columns out*8 + 2*sub + {0,1}.
// Independent of batch. Dims: (128+1) x 2048; row 128 is an always-zero guard
// so the scan's next-word prefetch needs no bounds check.
__device__ uint32_t g_pkw[129 * 2048];

static __device__ __forceinline__ __half2 u2h2(uint32_t u) {
    __half2 h; memcpy(&h, &u, 4); return h;
}
static __device__ __forceinline__ uint32_t h22u(__half2 h) {
    uint32_t u; memcpy(&u, &h, 4); return u;
}

// ---------------------------------------------------------------------------
// Pack kernel: binarize weight (>= 0.5), 2 bits per f (adjacent columns),
// 16 f per word. idx = fb16*2048 + (out*4 + sub); columns rem*2, rem*2+1.
// Blocks >= 1024 zero the guard row instead.
// ---------------------------------------------------------------------------
__global__ void pack_kernel(const float* __restrict__ w) {
    int idx = blockIdx.x * blockDim.x + threadIdx.x;
    if (idx >= 128 * 2048) {            // guard row: zeros
        if (idx < 129 * 2048) g_pkw[idx] = 0u;
        return;
    }
    int fb16 = idx >> 11;         // f-chunk of 16
    int rem  = idx & 2047;        // out*4 + sub -> column base = rem*2
    const float2* wp = reinterpret_cast<const float2*>(w) + rem;
    uint32_t word = 0;
#pragma unroll
    for (int j = 0; j < 16; j++) {
        float2 v = __ldg(wp + (size_t)(fb16 * 16 + j) * 2048);
        word |= ((v.x >= 0.5f ? 1u : 0u) | (v.y >= 0.5f ? 2u : 0u)) << (2 * j);
    }
    g_pkw[idx] = word;
}

// ---------------------------------------------------------------------------
// Scan kernel (R8, the measured optimum of this decomposition).
// Thread sub in {0..3} owns lanes {2sub, 2sub+1} of row-pair (b0, b0+8):
// half2 state A = lane 2sub, B = lane 2sub+1 (each packs the two batch rows).
// CSA step per half2: 6 fp16 fma ops (rel_err canary 0.0006271157):
//   m1=s*a; g1=fma(s,-2,1); r=fma(a,g1,s); mj=fma(c,r,m1);
//   g2=fma(r,-2,1); s'=fma(c,g2,r)
// SKEWED PIPELINE: iteration i runs A-step(f=i-1) then B-step(f=i);
// cB(i)=mjA(i) same-iteration register; cA(i-1)=neighbor mjB(i-2) via a shfl
// issued 2 iterations earlier. Both chains start from (s=0,c=0): a (0,0)-step
// yields exactly (s=a, c=0), so f=0 needs no special init.
// Grid: 128 blocks x 128 threads = 512 warps = 1 warp/SMSP on 128 SMs.
// Per-SMSP iteration ~ 21 issue slots + ~8 shfl toll ~= 32 cyc; fma-pipe hard
// floor is 24 cyc (12 HFMA2 x rt2) -- this config sits ~x1.3 off that floor.
// ---------------------------------------------------------------------------
__global__ void __launch_bounds__(128, 1)
scan_kernel(const float* __restrict__ x, float* __restrict__ out) {
    __shared__ uint32_t sx[IN_F];   // {half(x[b0,f]), half(x[b0+8,f])}

    const int tid = threadIdx.x;
    const int blk = blockIdx.x;
    const int b0 = blk >> 4;                 // 0..7 ; pair row is b0+8
    const int out_base = (blk & 15) << 5;    // 32 outs per block

    const float* xa = x + b0 * IN_F;
    const float* xb = x + (b0 + 8) * IN_F;
#pragma unroll
    for (int i = 0; i < IN_F / 128; i++) {
        int k = tid + i * 128;
        sx[k] = h22u(__halves2half2(__float2half(xa[k]), __float2half(xb[k])));
    }
    __syncthreads();

    const int sub  = tid & 3;
    const int lane = tid & 31;
    const int srcl = sub ? (lane - 1) : lane;       // carry source lane
    const uint32_t zmask = sub ? 0xFFFFFFFFu : 0u;  // lane-0 carry-in is 0
    const uint32_t* pk = g_pkw + out_base * 4 + tid;   // + fb16*2048 per chunk
    const __half2 neg2 = __float2half2_rn(-2.0f);
    const __half2 one  = __float2half2_rn(1.0f);
    const __half2 zero = __float2half2_rn(0.0f);

    // sign-extend bit `b` of v to a full mask
    auto sext = [](uint32_t v, int b) {
        return (uint32_t)(((int32_t)(v << (31 - b))) >> 31);
    };

    __half2 sA = zero, sB = zero;
    uint32_t p1 = 0, p2 = 0;            // shfl pipeline: p2 is 2 iters old

    // One pipelined iteration: A-step(f-1) then B-step(f).
    auto stepAB = [&](uint32_t mAu, uint32_t xuA, uint32_t mBu, uint32_t xuB) {
        // ---- A-step (f = i-1); cA = 2-iteration-old neighbor mjB ----
        __half2 aA  = u2h2(xuA & mAu);
        __half2 cAv = u2h2(p2 & zmask);
        __half2 m1A = __hmul2(sA, aA);
        __half2 g1A = __hfma2(sA, neg2, one);
        __half2 rA  = __hfma2(aA, g1A, sA);
        __half2 mjA = __hfma2(cAv, rA, m1A);
        __half2 g2A = __hfma2(rA, neg2, one);
        sA = __hfma2(cAv, g2A, rA);
        // ---- B-step (f = i); cB = mjA from THIS iteration ----
        __half2 aB  = u2h2(xuB & mBu);
        __half2 m1B = __hmul2(sB, aB);
        __half2 g1B = __hfma2(sB, neg2, one);
        __half2 rB  = __hfma2(aB, g1B, sB);
        __half2 mjB = __hfma2(mjA, rB, m1B);
        __half2 g2B = __hfma2(rB, neg2, one);
        sB = __hfma2(mjA, g2B, rB);
        // ---- carry exchange, consumed 2 iterations later ----
        p2 = p1;
        p1 = __shfl_sync(0xFFFFFFFFu, h22u(mjB), srcl);
    };

    const uint4* sx4 = reinterpret_cast<const uint4*>(sx);

    uint32_t w = __ldg(pk);
    uint32_t wprev = 0;                 // bits for f<0 read as 0 (identity)
    uint32_t xu_lag = 0;

#pragma unroll 1
    for (int fb16 = 0; fb16 < 128; fb16++) {
        // Unconditional: fb16 = 127 reads the zero guard row.
        uint32_t wnext = __ldg(pk + (fb16 + 1) * 2048);
        const uint4* p = sx4 + fb16 * 4;
        uint4 q0 = p[0], q1 = p[1], q2 = p[2], q3 = p[3];
        stepAB(sext(wprev, 30), xu_lag, sext(w, 1),  q0.x);
        stepAB(sext(w, 0),  q0.x, sext(w, 3),  q0.y);
        stepAB(sext(w, 2),  q0.y, sext(w, 5),  q0.z);
        stepAB(sext(w, 4),  q0.z, sext(w, 7),  q0.w);
        stepAB(sext(w, 6),  q0.w, sext(w, 9),  q1.x);
        stepAB(sext(w, 8),  q1.x, sext(w, 11), q1.y);
        stepAB(sext(w, 10), q1.y, sext(w, 13), q1.z);
        stepAB(sext(w, 12), q1.z, sext(w, 15), q1.w);
        stepAB(sext(w, 14), q1.w, sext(w, 17), q2.x);
        stepAB(sext(w, 16), q2.x, sext(w, 19), q2.y);
        stepAB(sext(w, 18), q2.y, sext(w, 21), q2.z);
        stepAB(sext(w, 20), q2.z, sext(w, 23), q2.w);
        stepAB(sext(w, 22), q2.w, sext(w, 25), q3.x);
        stepAB(sext(w, 24), q3.x, sext(w, 27), q3.y);
        stepAB(sext(w, 26), q3.y, sext(w, 29), q3.z);
        stepAB(sext(w, 28), q3.z, sext(w, 31), q3.w);
        xu_lag = q3.w;
        wprev = w;
        w = wnext;
    }

    // Drain: final A-step (f = 2047). cA = p2 = shfl(mjB(2046)).
    __half2 cB_fin, cA_fin;
    {
        uint32_t mAu = sext(wprev, 30);
        __half2 aA  = u2h2(xu_lag & mAu);
        __half2 cAv = u2h2(p2 & zmask);
        __half2 m1A = __hmul2(sA, aA);
        __half2 g1A = __hfma2(sA, neg2, one);
        __half2 rA  = __hfma2(aA, g1A, sA);
        __half2 mjA = __hfma2(cAv, rA, m1A);
        __half2 g2A = __hfma2(rA, neg2, one);
        sA = __hfma2(cAv, g2A, rA);
        cB_fin = mjA;                        // carry into lane 2sub+1
        cA_fin = u2h2(p1 & zmask);           // shfl(mjB(2047)) from last iter
    }

    // Output float32. Thread sub holds lanes (2sub, 2sub+1) of rows b0, b0+8.
    // s at out[b*4096 + o*8 + lane], c at +65536 floats.
    const int out_i = out_base + (tid >> 2);
    const int baseA = b0 * 4096 + out_i * 8 + 2 * sub;        // row b0
    const int baseB = baseA + 8 * 4096;                       // row b0+8
    float2 sAf = __half22float2(sA), cAf = __half22float2(cA_fin);
    float2 sBf = __half22float2(sB), cBf = __half22float2(cB_fin);
    out[baseA]             = sAf.x;   // row b0,   lane 2sub
    out[baseA + 1]         = sBf.x;   // row b0,   lane 2sub+1
    out[baseB]             = sAf.y;   // row b0+8, lane 2sub
    out[baseB + 1]         = sBf.y;
    out[65536 + baseA]     = cAf.x;
    out[65536 + baseA + 1] = cBf.x;
    out[65536 + baseB]     = cAf.y;
    out[65536 + baseB + 1] = cBf.y;
}

// ---------------------------------------------------------------------------
extern "C" void kernel_launch(void* const* d_in, const int* in_sizes, int n_in,
                              void* d_out, int out_size) {
    const float* x  = (const float*)d_in[0];   // (16, 2048) fp32
    const float* wt = (const float*)d_in[1];   // (2048, 4096) fp32
    float* out = (float*)d_out;                // 131072 fp32: [s | c]

    pack_kernel<<<1033, 256>>>(wt);            // 1024 data blocks + guard row
    scan_kernel<<<128, 128>>>(x, out);
}

// round 16
// speedup vs baseline: 1.4640x; 1.0110x over previous
#include <cuda_runtime.h>
#include <cuda_fp16.h>
#include <stdint.h>
#include <string.h>

// Problem constants
#define IN_F   2048
#define OUTF   512
#define NB     8
#define BATCH  16

// Packed bits: g_pkw[fb16][out*4+sub] : uint32. Bit pair (2j, 2j+1) holds the
// binarized weights for f = fb16*16 + j, columns out*8 + 2*sub + {0,1}.
// Independent of batch. Row 128 is an always-zero guard (prefetch needs no
// bounds check). Dims: 129 x 2048.
__device__ uint32_t g_pkw[129 * 2048];

static __device__ __forceinline__ __half2 u2h2(uint32_t u) {
    __half2 h; memcpy(&h, &u, 4); return h;
}
static __device__ __forceinline__ uint32_t h22u(__half2 h) {
    uint32_t u; memcpy(&u, &h, 4); return u;
}

// ---------------------------------------------------------------------------
// Pack kernel: binarize weight (>= 0.5), 2 bits per f (adjacent columns),
// 16 f per word. idx = fb16*2048 + (out*4 + sub); columns rem*2, rem*2+1.
// Blocks >= 1024 zero the guard row instead.
// ---------------------------------------------------------------------------
__global__ void pack_kernel(const float* __restrict__ w) {
    int idx = blockIdx.x * blockDim.x + threadIdx.x;
    if (idx >= 128 * 2048) {            // guard row: zeros
        if (idx < 129 * 2048) g_pkw[idx] = 0u;
        return;
    }
    int fb16 = idx >> 11;         // f-chunk of 16
    int rem  = idx & 2047;        // out*4 + sub -> column base = rem*2
    const float2* wp = reinterpret_cast<const float2*>(w) + rem;
    uint32_t word = 0;
#pragma unroll
    for (int j = 0; j < 16; j++) {
        float2 v = __ldg(wp + (size_t)(fb16 * 16 + j) * 2048);
        word |= ((v.x >= 0.5f ? 1u : 0u) | (v.y >= 0.5f ? 2u : 0u)) << (2 * j);
    }
    g_pkw[idx] = word;
}

// ---------------------------------------------------------------------------
// Scan kernel (R8 structure -- the measured optimum of this decomposition --
// with the shfl pipeline ping-ponged across an unroll-2 so the p2=p1 MOV
// disappears and ptxas schedules across a 2-iteration window).
// Thread sub in {0..3} owns lanes {2sub, 2sub+1} of row-pair (b0, b0+8):
// half2 state A = lane 2sub, B = lane 2sub+1 (each packs the two batch rows).
// CSA step per half2: 6 fp16 fma ops (rel_err canary 0.0006271157):
//   m1=s*a; g1=fma(s,-2,1); r=fma(a,g1,s); mj=fma(c,r,m1);
//   g2=fma(r,-2,1); s'=fma(c,g2,r)
// SKEWED PIPELINE: iteration i runs A-step(f=i-1) then B-step(f=i);
// cB(i)=mjA(i) same-iteration register; cA(i-1)=neighbor mjB(i-2) via a shfl
// issued 2 iterations earlier (ping-pong registers pA/pB, no rotation MOV).
// Both chains start from (s=0,c=0): a (0,0)-step yields exactly (s=a, c=0).
// Grid: 128 blocks x 128 threads = 512 warps = 1 warp/SMSP on 128 SMs.
// Floor: 12 HFMA2 x rt2 = 24 cyc/iter on the fma pipe; we run ~1.1x that.
// ---------------------------------------------------------------------------
__global__ void __launch_bounds__(128, 1)
scan_kernel(const float* __restrict__ x, float* __restrict__ out) {
    __shared__ uint32_t sx[IN_F];   // {half(x[b0,f]), half(x[b0+8,f])}

    const int tid = threadIdx.x;
    const int blk = blockIdx.x;
    const int b0 = blk >> 4;                 // 0..7 ; pair row is b0+8
    const int out_base = (blk & 15) << 5;    // 32 outs per block

    const float* xa = x + b0 * IN_F;
    const float* xb = x + (b0 + 8) * IN_F;
#pragma unroll
    for (int i = 0; i < IN_F / 128; i++) {
        int k = tid + i * 128;
        sx[k] = h22u(__halves2half2(__float2half(xa[k]), __float2half(xb[k])));
    }
    __syncthreads();

    const int sub  = tid & 3;
    const int lane = tid & 31;
    const int srcl = sub ? (lane - 1) : lane;       // carry source lane
    const uint32_t zmask = sub ? 0xFFFFFFFFu : 0u;  // lane-0 carry-in is 0
    const uint32_t* pk = g_pkw + out_base * 4 + tid;   // + fb16*2048 per chunk
    const __half2 neg2 = __float2half2_rn(-2.0f);
    const __half2 one  = __float2half2_rn(1.0f);
    const __half2 zero = __float2half2_rn(0.0f);

    // sign-extend bit `b` of v to a full mask
    auto sext = [](uint32_t v, int b) {
        return (uint32_t)(((int32_t)(v << (31 - b))) >> 31);
    };

    __half2 sA = zero, sB = zero;
    uint32_t pA = 0, pB = 0;   // ping-pong shfl pipeline (each 2 iters of slack)

    // One pipelined iteration: A-step(f-1) then B-step(f).
    // pOld: shfl result from 2 iterations ago (consumed as cA).
    // pNew: overwritten with this iteration's shfl (consumed 2 iters later).
    auto stepAB = [&](uint32_t mAu, uint32_t xuA, uint32_t mBu, uint32_t xuB,
                      uint32_t& pOld, uint32_t& pNew) {
        // ---- A-step (f = i-1); cA = 2-iteration-old neighbor mjB ----
        __half2 aA  = u2h2(xuA & mAu);
        __half2 cAv = u2h2(pOld & zmask);
        __half2 m1A = __hmul2(sA, aA);
        __half2 g1A = __hfma2(sA, neg2, one);
        __half2 rA  = __hfma2(aA, g1A, sA);
        __half2 mjA = __hfma2(cAv, rA, m1A);
        __half2 g2A = __hfma2(rA, neg2, one);
        sA = __hfma2(cAv, g2A, rA);
        // ---- B-step (f = i); cB = mjA from THIS iteration ----
        __half2 aB  = u2h2(xuB & mBu);
        __half2 m1B = __hmul2(sB, aB);
        __half2 g1B = __hfma2(sB, neg2, one);
        __half2 rB  = __hfma2(aB, g1B, sB);
        __half2 mjB = __hfma2(mjA, rB, m1B);
        __half2 g2B = __hfma2(rB, neg2, one);
        sB = __hfma2(mjA, g2B, rB);
        // ---- carry exchange: slot freed by pOld is refilled ----
        pOld = __shfl_sync(0xFFFFFFFFu, h22u(mjB), srcl);
        (void)pNew;
    };

    const uint4* sx4 = reinterpret_cast<const uint4*>(sx);

    uint32_t w = __ldg(pk);
    uint32_t wprev = 0;                 // bits for f<0 read as 0 (identity)
    uint32_t xu_lag = 0;

#pragma unroll 1
    for (int fb16 = 0; fb16 < 128; fb16++) {
        // Unconditional: fb16 = 127 reads the zero guard row.
        uint32_t wnext = __ldg(pk + (fb16 + 1) * 2048);
        const uint4* p = sx4 + fb16 * 4;
        uint4 q0 = p[0], q1 = p[1], q2 = p[2], q3 = p[3];
        // Ping-pong: even steps consume/refill pA, odd steps pB.
        stepAB(sext(wprev, 30), xu_lag, sext(w, 1),  q0.x, pA, pB);
        stepAB(sext(w, 0),  q0.x, sext(w, 3),  q0.y, pB, pA);
        stepAB(sext(w, 2),  q0.y, sext(w, 5),  q0.z, pA, pB);
        stepAB(sext(w, 4),  q0.z, sext(w, 7),  q0.w, pB, pA);
        stepAB(sext(w, 6),  q0.w, sext(w, 9),  q1.x, pA, pB);
        stepAB(sext(w, 8),  q1.x, sext(w, 11), q1.y, pB, pA);
        stepAB(sext(w, 10), q1.y, sext(w, 13), q1.z, pA, pB);
        stepAB(sext(w, 12), q1.z, sext(w, 15), q1.w, pB, pA);
        stepAB(sext(w, 14), q1.w, sext(w, 17), q2.x, pA, pB);
        stepAB(sext(w, 16), q2.x, sext(w, 19), q2.y, pB, pA);
        stepAB(sext(w, 18), q2.y, sext(w, 21), q2.z, pA, pB);
        stepAB(sext(w, 20), q2.z, sext(w, 23), q2.w, pB, pA);
        stepAB(sext(w, 22), q2.w, sext(w, 25), q3.x, pA, pB);
        stepAB(sext(w, 24), q3.x, sext(w, 27), q3.y, pB, pA);
        stepAB(sext(w, 26), q3.y, sext(w, 29), q3.z, pA, pB);
        stepAB(sext(w, 28), q3.z, sext(w, 31), q3.w, pB, pA);
        xu_lag = q3.w;
        wprev = w;
        w = wnext;
    }
    // After 2048 iterations (even count), the ping-pong state is:
    //   pA = shfl from iteration 2046 (2 iters old)  -> cA for f=2047
    //   pB = shfl from iteration 2047 (1 iter old)   -> final cA output

    // Drain: final A-step (f = 2047).
    __half2 cB_fin, cA_fin;
    {
        uint32_t mAu = sext(wprev, 30);
        __half2 aA  = u2h2(xu_lag & mAu);
        __half2 cAv = u2h2(pA & zmask);
        __half2 m1A = __hmul2(sA, aA);
        __half2 g1A = __hfma2(sA, neg2, one);
        __half2 rA  = __hfma2(aA, g1A, sA);
        __half2 mjA = __hfma2(cAv, rA, m1A);
        __half2 g2A = __hfma2(rA, neg2, one);
        sA = __hfma2(cAv, g2A, rA);
        cB_fin = mjA;                        // carry into lane 2sub+1
        cA_fin = u2h2(pB & zmask);           // shfl(mjB(2047))
    }

    // Output float32. Thread sub holds lanes (2sub, 2sub+1) of rows b0, b0+8.
    // s at out[b*4096 + o*8 + lane], c at +65536 floats.
    const int out_i = out_base + (tid >> 2);
    const int baseA = b0 * 4096 + out_i * 8 + 2 * sub;        // row b0
    const int baseB = baseA + 8 * 4096;                       // row b0+8
    float2 sAf = __half22float2(sA), cAf = __half22float2(cA_fin);
    float2 sBf = __half22float2(sB), cBf = __half22float2(cB_fin);
    out[baseA]             = sAf.x;   // row b0,   lane 2sub
    out[baseA + 1]         = sBf.x;   // row b0,   lane 2sub+1
    out[baseB]             = sAf.y;   // row b0+8, lane 2sub
    out[baseB + 1]         = sBf.y;
    out[65536 + baseA]     = cAf.x;
    out[65536 + baseA + 1] = cBf.x;
    out[65536 + baseB]     = cAf.y;
    out[65536 + baseB + 1] = cBf.y;
}

// ---------------------------------------------------------------------------
extern "C" void kernel_launch(void* const* d_in, const int* in_sizes, int n_in,
                              void* d_out, int out_size) {
    const float* x  = (const float*)d_in[0];   // (16, 2048) fp32
    const float* wt = (const float*)d_in[1];   // (2048, 4096) fp32
    float* out = (float*)d_out;                // 131072 fp32: [s | c]

    pack_kernel<<<1033, 256>>>(wt);            // 1024 data blocks + guard row
    scan_kernel<<<128, 128>>>(x, out);
}

// round 17
// speedup vs baseline: 1.4715x; 1.0052x over previous
#include <cuda_runtime.h>
#include <cuda_fp16.h>
#include <stdint.h>
#include <string.h>

// Problem constants
#define IN_F   2048
#define OUTF   512
#define NB     8
#define BATCH  16

// Packed bits: g_pkw[fb16][out*4+sub] : uint32. Bit pair (2j, 2j+1) holds the
// binarized weights for f = fb16*16 + j, columns out*8 + 2*sub + {0,1}.
// Independent of batch. Row 128 is an always-zero guard (prefetch needs no
// bounds check). Dims: 129 x 2048.
__device__ uint32_t g_pkw[129 * 2048];

static __device__ __forceinline__ __half2 u2h2(uint32_t u) {
    __half2 h; memcpy(&h, &u, 4); return h;
}
static __device__ __forceinline__ uint32_t h22u(__half2 h) {
    uint32_t u; memcpy(&u, &h, 4); return u;
}

// ---------------------------------------------------------------------------
// Pack kernel: binarize weight (>= 0.5), 2 bits per f (adjacent columns),
// 16 f per word. idx = fb16*2048 + (out*4 + sub); columns rem*2, rem*2+1.
// Blocks >= 1024 zero the guard row instead.
// ---------------------------------------------------------------------------
__global__ void pack_kernel(const float* __restrict__ w) {
    int idx = blockIdx.x * blockDim.x + threadIdx.x;
    if (idx >= 128 * 2048) {            // guard row: zeros
        if (idx < 129 * 2048) g_pkw[idx] = 0u;
        return;
    }
    int fb16 = idx >> 11;         // f-chunk of 16
    int rem  = idx & 2047;        // out*4 + sub -> column base = rem*2
    const float2* wp = reinterpret_cast<const float2*>(w) + rem;
    uint32_t word = 0;
#pragma unroll
    for (int j = 0; j < 16; j++) {
        float2 v = __ldg(wp + (size_t)(fb16 * 16 + j) * 2048);
        word |= ((v.x >= 0.5f ? 1u : 0u) | (v.y >= 0.5f ? 2u : 0u)) << (2 * j);
    }
    g_pkw[idx] = word;
}

// ---------------------------------------------------------------------------
// Scan kernel (R16 + one-quad LDS lookahead: quad q+1 is loaded before the
// 4 steps of quad q execute, hiding the 29-cyc smem latency; +4 regs only).
// Thread sub in {0..3} owns lanes {2sub, 2sub+1} of row-pair (b0, b0+8):
// half2 state A = lane 2sub, B = lane 2sub+1 (each packs the two batch rows).
// CSA step per half2: 6 fp16 fma ops (rel_err canary 0.0006271157):
//   m1=s*a; g1=fma(s,-2,1); r=fma(a,g1,s); mj=fma(c,r,m1);
//   g2=fma(r,-2,1); s'=fma(c,g2,r)
// SKEWED PIPELINE: iteration i runs A-step(f=i-1) then B-step(f=i);
// cB(i)=mjA(i) same-iteration register; cA(i-1)=neighbor mjB(i-2) via a shfl
// issued 2 iterations earlier (ping-pong registers pA/pB, no rotation MOV).
// Both chains start from (s=0,c=0): a (0,0)-step yields exactly (s=a, c=0).
// Grid: 128 blocks x 128 threads = 512 warps = 1 warp/SMSP on 128 SMs.
// ---------------------------------------------------------------------------
__global__ void __launch_bounds__(128, 1)
scan_kernel(const float* __restrict__ x, float* __restrict__ out) {
    __shared__ uint32_t sx[IN_F + 4];   // {half(x[b0,f]), half(x[b0+8,f])}; +pad

    const int tid = threadIdx.x;
    const int blk = blockIdx.x;
    const int b0 = blk >> 4;                 // 0..7 ; pair row is b0+8
    const int out_base = (blk & 15) << 5;    // 32 outs per block

    const float* xa = x + b0 * IN_F;
    const float* xb = x + (b0 + 8) * IN_F;
#pragma unroll
    for (int i = 0; i < IN_F / 128; i++) {
        int k = tid + i * 128;
        sx[k] = h22u(__halves2half2(__float2half(xa[k]), __float2half(xb[k])));
    }
    if (tid < 4) sx[IN_F + tid] = 0;         // pad for the final quad prefetch
    __syncthreads();

    const int sub  = tid & 3;
    const int lane = tid & 31;
    const int srcl = sub ? (lane - 1) : lane;       // carry source lane
    const uint32_t zmask = sub ? 0xFFFFFFFFu : 0u;  // lane-0 carry-in is 0
    const uint32_t* pk = g_pkw + out_base * 4 + tid;   // + fb16*2048 per chunk
    const __half2 neg2 = __float2half2_rn(-2.0f);
    const __half2 one  = __float2half2_rn(1.0f);
    const __half2 zero = __float2half2_rn(0.0f);

    // sign-extend bit `b` of v to a full mask
    auto sext = [](uint32_t v, int b) {
        return (uint32_t)(((int32_t)(v << (31 - b))) >> 31);
    };

    __half2 sA = zero, sB = zero;
    uint32_t pA = 0, pB = 0;   // ping-pong shfl pipeline (each 2 iters of slack)

    // One pipelined iteration: A-step(f-1) then B-step(f).
    auto stepAB = [&](uint32_t mAu, uint32_t xuA, uint32_t mBu, uint32_t xuB,
                      uint32_t& pOld) {
        // ---- A-step (f = i-1); cA = 2-iteration-old neighbor mjB ----
        __half2 aA  = u2h2(xuA & mAu);
        __half2 cAv = u2h2(pOld & zmask);
        __half2 m1A = __hmul2(sA, aA);
        __half2 g1A = __hfma2(sA, neg2, one);
        __half2 rA  = __hfma2(aA, g1A, sA);
        __half2 mjA = __hfma2(cAv, rA, m1A);
        __half2 g2A = __hfma2(rA, neg2, one);
        sA = __hfma2(cAv, g2A, rA);
        // ---- B-step (f = i); cB = mjA from THIS iteration ----
        __half2 aB  = u2h2(xuB & mBu);
        __half2 m1B = __hmul2(sB, aB);
        __half2 g1B = __hfma2(sB, neg2, one);
        __half2 rB  = __hfma2(aB, g1B, sB);
        __half2 mjB = __hfma2(mjA, rB, m1B);
        __half2 g2B = __hfma2(rB, neg2, one);
        sB = __hfma2(mjA, g2B, rB);
        // ---- carry exchange: slot freed by pOld is refilled ----
        pOld = __shfl_sync(0xFFFFFFFFu, h22u(mjB), srcl);
    };

    const uint4* sx4 = reinterpret_cast<const uint4*>(sx);

    uint32_t w = __ldg(pk);
    uint32_t wprev = 0;                 // bits for f<0 read as 0 (identity)
    uint32_t xu_lag = 0;

    uint4 qc = sx4[0];                  // current quad (lookahead pipeline)

#pragma unroll 1
    for (int fb16 = 0; fb16 < 128; fb16++) {
        // Unconditional: fb16 = 127 reads the zero guard row.
        uint32_t wnext = __ldg(pk + (fb16 + 1) * 2048);
        const int qi = fb16 * 4;
        // group 0 (f = 16*fb16 + 0..3); prefetch quad qi+1 first
        uint4 qn = sx4[qi + 1];
        stepAB(sext(wprev, 30), xu_lag, sext(w, 1),  qc.x, pA);
        stepAB(sext(w, 0),  qc.x, sext(w, 3),  qc.y, pB);
        stepAB(sext(w, 2),  qc.y, sext(w, 5),  qc.z, pA);
        stepAB(sext(w, 4),  qc.z, sext(w, 7),  qc.w, pB);
        uint32_t xl = qc.w; qc = qn;
        // group 1 (f = +4..7)
        qn = sx4[qi + 2];
        stepAB(sext(w, 6),  xl,   sext(w, 9),  qc.x, pA);
        stepAB(sext(w, 8),  qc.x, sext(w, 11), qc.y, pB);
        stepAB(sext(w, 10), qc.y, sext(w, 13), qc.z, pA);
        stepAB(sext(w, 12), qc.z, sext(w, 15), qc.w, pB);
        xl = qc.w; qc = qn;
        // group 2 (f = +8..11)
        qn = sx4[qi + 3];
        stepAB(sext(w, 14), xl,   sext(w, 17), qc.x, pA);
        stepAB(sext(w, 16), qc.x, sext(w, 19), qc.y, pB);
        stepAB(sext(w, 18), qc.y, sext(w, 21), qc.z, pA);
        stepAB(sext(w, 20), qc.z, sext(w, 23), qc.w, pB);
        xl = qc.w; qc = qn;
        // group 3 (f = +12..15); prefetch next chunk's quad 0 (pad at end)
        qn = sx4[qi + 4];
        stepAB(sext(w, 22), xl,   sext(w, 25), qc.x, pA);
        stepAB(sext(w, 24), qc.x, sext(w, 27), qc.y, pB);
        stepAB(sext(w, 26), qc.y, sext(w, 29), qc.z, pA);
        stepAB(sext(w, 28), qc.z, sext(w, 31), qc.w, pB);
        xu_lag = qc.w; qc = qn;
        wprev = w;
        w = wnext;
    }
    // 2048 iterations ran (even count): pA = shfl from iter 2046 (2 old),
    // pB = shfl from iter 2047 (1 old).

    // Drain: final A-step (f = 2047).
    __half2 cB_fin, cA_fin;
    {
        uint32_t mAu = sext(wprev, 30);
        __half2 aA  = u2h2(xu_lag & mAu);
        __half2 cAv = u2h2(pA & zmask);
        __half2 m1A = __hmul2(sA, aA);
        __half2 g1A = __hfma2(sA, neg2, one);
        __half2 rA  = __hfma2(aA, g1A, sA);
        __half2 mjA = __hfma2(cAv, rA, m1A);
        __half2 g2A = __hfma2(rA, neg2, one);
        sA = __hfma2(cAv, g2A, rA);
        cB_fin = mjA;                        // carry into lane 2sub+1
        cA_fin = u2h2(pB & zmask);           // shfl(mjB(2047))
    }

    // Output float32. Thread sub holds lanes (2sub, 2sub+1) of rows b0, b0+8.
    // s at out[b*4096 + o*8 + lane], c at +65536 floats.
    const int out_i = out_base + (tid >> 2);
    const int baseA = b0 * 4096 + out_i * 8 + 2 * sub;        // row b0
    const int baseB = baseA + 8 * 4096;                       // row b0+8
    float2 sAf = __half22float2(sA), cAf = __half22float2(cA_fin);
    float2 sBf = __half22float2(sB), cBf = __half22float2(cB_fin);
    out[baseA]             = sAf.x;   // row b0,   lane 2sub
    out[baseA + 1]         = sBf.x;   // row b0,   lane 2sub+1
    out[baseB]             = sAf.y;   // row b0+8, lane 2sub
    out[baseB + 1]         = sBf.y;
    out[65536 + baseA]     = cAf.x;
    out[65536 + baseA + 1] = cBf.x;
    out[65536 + baseB]     = cAf.y;
    out[65536 + baseB + 1] = cBf.y;
}

// ---------------------------------------------------------------------------
extern "C" void kernel_launch(void* const* d_in, const int* in_sizes, int n_in,
                              void* d_out, int out_size) {
    const float* x  = (const float*)d_in[0];   // (16, 2048) fp32
    const float* wt = (const float*)d_in[1];   // (2048, 4096) fp32
    float* out = (float*)d_out;                // 131072 fp32: [s | c]

    pack_kernel<<<1033, 256>>>(wt);            // 1024 data blocks + guard row
    scan_kernel<<<128, 128>>>(x, out);
}